// round 3
// baseline (speedup 1.0000x reference)
#include <cuda_runtime.h>
#include <cstddef>

#define LEN 2048
#define DIM 512

// Precomputed: G[a][p][d][r], a<64, p<2, d<512, r<8  (2MB each)
__device__ float g_Gk[64 * 2 * 512 * 8];
__device__ float g_Gv[64 * 2 * 512 * 8];
__device__ float g_bkf[64 * 2 * 8];
__device__ float g_bvf[64 * 2 * 8];

typedef unsigned long long u64;
__device__ __forceinline__ u64 pack2(float x, float y) {
    u64 r; asm("mov.b64 %0,{%1,%2};" : "=l"(r) : "f"(x), "f"(y)); return r;
}
__device__ __forceinline__ u64 dup2(float x) {
    u64 r; asm("mov.b64 %0,{%1,%1};" : "=l"(r) : "f"(x)); return r;
}
__device__ __forceinline__ void unpack2(u64 v, float &x, float &y) {
    asm("mov.b64 {%0,%1},%2;" : "=f"(x), "=f"(y) : "l"(v));
}
__device__ __forceinline__ void fma2(u64 &a, u64 b, u64 c) {
    asm("fma.rn.f32x2 %0,%1,%2,%0;" : "+l"(a) : "l"(b), "l"(c));
}

// ================= Kernel 1: G[a][p][d][r] = sum_l W[256p+l,d]*f[a,l,r] =================
__global__ void __launch_bounds__(256) precompute_kernel(
    const float* __restrict__ Wk, const float* __restrict__ bk,
    const float* __restrict__ Wv, const float* __restrict__ bv,
    const float* __restrict__ fac)
{
    __shared__ float f_s[256 * 8];
    __shared__ float bks[256], bvs[256];
    const int a = blockIdx.x >> 1, p = blockIdx.x & 1;
    const int t = threadIdx.x;

    const float* fa = fac + a * (256 * 8);
    for (int i = t; i < 2048; i += 256) f_s[i] = fa[i];
    bks[t] = bk[256 * p + t];
    bvs[t] = bv[256 * p + t];
    __syncthreads();

    u64 gk2[8], gv2[8];
#pragma unroll
    for (int r = 0; r < 8; r++) { gk2[r] = 0ull; gv2[r] = 0ull; }

    const int d0 = t, d1 = t + 256;
    for (int l = 0; l < 256; l++) {
        const float* wkr = Wk + (size_t)(256 * p + l) * 512;
        const float* wvr = Wv + (size_t)(256 * p + l) * 512;
        u64 wk = pack2(wkr[d0], wkr[d1]);
        u64 wv = pack2(wvr[d0], wvr[d1]);
        float4 fA = *(const float4*)&f_s[l * 8];
        float4 fB = *(const float4*)&f_s[l * 8 + 4];
        float fr[8] = {fA.x, fA.y, fA.z, fA.w, fB.x, fB.y, fB.z, fB.w};
#pragma unroll
        for (int r = 0; r < 8; r++) {
            u64 fd = dup2(fr[r]);
            fma2(gk2[r], wk, fd);
            fma2(gv2[r], wv, fd);
        }
    }
    float* gko = g_Gk + a * 8192 + (p * 512) * 8;
    float* gvo = g_Gv + a * 8192 + (p * 512) * 8;
    float gk[2][8], gv[2][8];
#pragma unroll
    for (int r = 0; r < 8; r++) {
        unpack2(gk2[r], gk[0][r], gk[1][r]);
        unpack2(gv2[r], gv[0][r], gv[1][r]);
    }
#pragma unroll
    for (int u = 0; u < 2; u++) {
        int d = u ? d1 : d0;
        *(float4*)&gko[d * 8]     = make_float4(gk[u][0], gk[u][1], gk[u][2], gk[u][3]);
        *(float4*)&gko[d * 8 + 4] = make_float4(gk[u][4], gk[u][5], gk[u][6], gk[u][7]);
        *(float4*)&gvo[d * 8]     = make_float4(gv[u][0], gv[u][1], gv[u][2], gv[u][3]);
        *(float4*)&gvo[d * 8 + 4] = make_float4(gv[u][4], gv[u][5], gv[u][6], gv[u][7]);
    }
    if (t < 16) {
        int r = t & 7;
        const float* bb = (t < 8) ? bks : bvs;
        float acc = 0.f;
        for (int l = 0; l < 256; l++) acc += bb[l] * f_s[l * 8 + r];
        if (t < 8) g_bkf[(a * 2 + p) * 8 + r] = acc;
        else       g_bvf[(a * 2 + p) * 8 + r] = acc;
    }
}

// ================= Kernel 2: fused attention, one block per (a, batch-pair) =============
// smem layout (float offsets)
#define OFF_G    0        // 16384: G staged, k then v, each [(p*512+d)*8+r]
#define OFF_M    16384    // 16384: m[(p*512+d)*16 + b*8 + r]
#define OFF_X    32768    // 16384: xs[32][512]; reused as 2 Wq tiles [256][20]
#define OFF_KV   49152    // 2048:  ((b*2+mat)*64 + h)*8 + r
#define OFF_S    51200    // 32:    (b*2+p)*8 + r
#define OFF_VT   51232    // 1024:  (b*8+r)*64 + h
#define OFF_ATTN 52256    // 4096:  (b*256+l)*8 + r
#define OFF_BQ   56352    // 512
#define SMEM_FLOATS 56864
#define SMEM_BYTES (SMEM_FLOATS * 4)

__global__ void __launch_bounds__(256, 1) attn_kernel(
    const float* __restrict__ x, const float* __restrict__ Wq,
    const float* __restrict__ bq, float* __restrict__ out)
{
    extern __shared__ float sm[];
    const int t = threadIdx.x;
    const int a = blockIdx.y;
    const int b0 = blockIdx.x * 2;

    // stage G slab + bq
    {
        const float4* gk = (const float4*)(g_Gk + a * 8192);
        const float4* gv = (const float4*)(g_Gv + a * 8192);
        float4* dst = (float4*)(sm + OFF_G);
#pragma unroll
        for (int i = 0; i < 8; i++) dst[t + i * 256] = gk[t + i * 256];
#pragma unroll
        for (int i = 0; i < 8; i++) dst[2048 + t + i * 256] = gv[t + i * 256];
        sm[OFF_BQ + t] = bq[t];
        sm[OFF_BQ + 256 + t] = bq[256 + t];
    }

    const int h  = t >> 2;          // 0..63
    const int rp = t & 3;           // r-pair
    const int pp = h & 1;
    const int row = h >> 1;         // 0..31
    const float2 bk2 = *(const float2*)(g_bkf + (a * 2 + pp) * 8 + 2 * rp);
    const float2 bv2 = *(const float2*)(g_bvf + (a * 2 + pp) * 8 + 2 * rp);

    for (int bi = 0; bi < 2; bi++) {
        const int b = b0 + bi;
        __syncthreads();  // guards G staging (bi=0) / xs reuse (bi=1)
        {   // load x tile [32,512]
            const float4* xsrc = (const float4*)(x + ((size_t)b * LEN + (size_t)a * 32) * DIM);
            float4* xdst = (float4*)(sm + OFF_X);
#pragma unroll
            for (int i = 0; i < 16; i++) xdst[t + i * 256] = xsrc[t + i * 256];
        }
        __syncthreads();

        // step 1: k'[h,r], v'[h,r] = sum_d x[row,d]*G[p][d][r] + bias
        {
            u64 acck = pack2(bk2.x, bk2.y);
            u64 accv = pack2(bv2.x, bv2.y);
            const float* xr  = sm + OFF_X + row * 512;
            const float* gkp = sm + OFF_G + pp * 4096 + 2 * rp;
            const float* gvp = sm + OFF_G + 8192 + pp * 4096 + 2 * rp;
#pragma unroll 8
            for (int d = 0; d < 512; d++) {
                u64 xv = dup2(xr[d]);
                fma2(acck, xv, *(const u64*)(gkp + d * 8));
                fma2(accv, xv, *(const u64*)(gvp + d * 8));
            }
            *(u64*)(sm + OFF_KV + ((size_t)(bi * 2 + 0) * 64 + h) * 8 + 2 * rp) = acck;
            *(u64*)(sm + OFF_KV + ((size_t)(bi * 2 + 1) * 64 + h) * 8 + 2 * rp) = accv;
            float v0, v1; unpack2(accv, v0, v1);
            sm[OFF_VT + (bi * 8 + 2 * rp)     * 64 + h] = v0;
            sm[OFF_VT + (bi * 8 + 2 * rp + 1) * 64 + h] = v1;
        }
        __syncthreads();

        // step 2: m[p][d][r] = sum_j x[j,d] * k'[2j+p,r]
        {
            u64 macc[2][2][4];
#pragma unroll
            for (int p = 0; p < 2; p++)
#pragma unroll
                for (int u = 0; u < 2; u++)
#pragma unroll
                    for (int q = 0; q < 4; q++) macc[p][u][q] = 0ull;
            const float* xcol = sm + OFF_X;
            const u64* kvb = (const u64*)(sm + OFF_KV + (size_t)(bi * 2) * 64 * 8);
#pragma unroll 2
            for (int j = 0; j < 32; j++) {
                u64 x0 = dup2(xcol[j * 512 + t]);
                u64 x1 = dup2(xcol[j * 512 + t + 256]);
#pragma unroll
                for (int p = 0; p < 2; p++)
#pragma unroll
                    for (int q = 0; q < 4; q++) {
                        u64 kk = kvb[(size_t)(2 * j + p) * 4 + q];
                        fma2(macc[p][0][q], x0, kk);
                        fma2(macc[p][1][q], x1, kk);
                    }
            }
#pragma unroll
            for (int p = 0; p < 2; p++)
#pragma unroll
                for (int u = 0; u < 2; u++) {
                    int d = t + u * 256;
                    u64* mdst = (u64*)(sm + OFF_M + (size_t)(p * 512 + d) * 16 + bi * 8);
#pragma unroll
                    for (int q = 0; q < 4; q++) mdst[q] = macc[p][u][q];
                }
        }
    }
    __syncthreads();
    // s[b][p][r] = sum_j k'[2j+p,r]  (bq fold)
    if (t < 32) {
        int b = t >> 4, p = (t >> 3) & 1, r = t & 7;
        float acc = 0.f;
        for (int j = 0; j < 32; j++)
            acc += sm[OFF_KV + ((size_t)(b * 2) * 64 + 2 * j + p) * 8 + r];
        sm[OFF_S + (b * 2 + p) * 8 + r] = acc;
    }
    __syncthreads();

    // step 3: scores[l,(b,r)] = sum_{p,d} Wq[256p+l,d]*m[p][d][b*8+r]
    const int l = t;
    u64 acc[2][4];
#pragma unroll
    for (int b = 0; b < 2; b++)
#pragma unroll
        for (int q = 0; q < 4; q++) acc[b][q] = 0ull;

    float* tile = sm + OFF_X;  // two buffers of 256*20 floats
    float4 ld[4];
    {   // prologue: tile 0 (p=0, dbase=0)
#pragma unroll
        for (int j = 0; j < 4; j++) {
            int f4 = j * 256 + t, ll = f4 >> 2, k4 = f4 & 3;
            ld[j] = *(const float4*)(Wq + (size_t)ll * 512 + k4 * 4);
        }
#pragma unroll
        for (int j = 0; j < 4; j++) {
            int f4 = j * 256 + t, ll = f4 >> 2, k4 = f4 & 3;
            *(float4*)(tile + ll * 20 + k4 * 4) = ld[j];
        }
    }
    __syncthreads();

    for (int kt = 0; kt < 64; kt++) {
        const int cur = kt & 1;
        if (kt < 63) {
            int ks = (kt + 1) * 16, p = ks >> 9, dbase = ks & 511;
#pragma unroll
            for (int j = 0; j < 4; j++) {
                int f4 = j * 256 + t, ll = f4 >> 2, k4 = f4 & 3;
                ld[j] = *(const float4*)(Wq + (size_t)(256 * p + ll) * 512 + dbase + k4 * 4);
            }
        }
        {
            int ks = kt * 16, p = ks >> 9, dbase = ks & 511;
            const float4* trow = (const float4*)(tile + cur * 5120 + l * 20);
            float4 w0 = trow[0], w1 = trow[1], w2 = trow[2], w3 = trow[3];
            float wq[16] = {w0.x, w0.y, w0.z, w0.w, w1.x, w1.y, w1.z, w1.w,
                            w2.x, w2.y, w2.z, w2.w, w3.x, w3.y, w3.z, w3.w};
            const u64* mrow = (const u64*)(sm + OFF_M) + (size_t)(p * 512 + dbase) * 8;
#pragma unroll
            for (int dd = 0; dd < 16; dd++) {
                u64 wv = dup2(wq[dd]);
                const u64* mp = mrow + dd * 8;
                fma2(acc[0][0], wv, mp[0]); fma2(acc[0][1], wv, mp[1]);
                fma2(acc[0][2], wv, mp[2]); fma2(acc[0][3], wv, mp[3]);
                fma2(acc[1][0], wv, mp[4]); fma2(acc[1][1], wv, mp[5]);
                fma2(acc[1][2], wv, mp[6]); fma2(acc[1][3], wv, mp[7]);
            }
        }
        __syncthreads();
        if (kt < 63) {
            int nxt = (kt + 1) & 1;
#pragma unroll
            for (int j = 0; j < 4; j++) {
                int f4 = j * 256 + t, ll = f4 >> 2, k4 = f4 & 3;
                *(float4*)(tile + nxt * 5120 + ll * 20 + k4 * 4) = ld[j];
            }
            __syncthreads();
        }
    }

    // bias fold + scale + softmax over r (thread-local)
    {
        const u64 dq0 = dup2(sm[OFF_BQ + l]);
        const u64 dq1 = dup2(sm[OFF_BQ + 256 + l]);
#pragma unroll
        for (int b = 0; b < 2; b++) {
            const u64* sp0 = (const u64*)(sm + OFF_S + (b * 2 + 0) * 8);
            const u64* sp1 = (const u64*)(sm + OFF_S + (b * 2 + 1) * 8);
#pragma unroll
            for (int q = 0; q < 4; q++) { fma2(acc[b][q], dq0, sp0[q]); fma2(acc[b][q], dq1, sp1[q]); }
            float f[8];
            unpack2(acc[b][0], f[0], f[1]); unpack2(acc[b][1], f[2], f[3]);
            unpack2(acc[b][2], f[4], f[5]); unpack2(acc[b][3], f[6], f[7]);
            float mx = f[0];
#pragma unroll
            for (int r = 1; r < 8; r++) mx = fmaxf(mx, f[r]);
            float e[8], ssum = 0.f;
#pragma unroll
            for (int r = 0; r < 8; r++) { e[r] = __expf((f[r] - mx) * 0.125f); ssum += e[r]; }
            float inv = 1.0f / ssum;
#pragma unroll
            for (int r = 0; r < 8; r++) sm[OFF_ATTN + ((size_t)(b * 256 + l)) * 8 + r] = e[r] * inv;
        }
    }
    __syncthreads();

    // step 4: out[l,h] = sum_r attn[l,r]*v'[h,r], coalesced float4 stores
#pragma unroll
    for (int b = 0; b < 2; b++) {
        const float* attb = sm + OFF_ATTN + (size_t)b * 256 * 8;
        const float* vtb  = sm + OFF_VT + (size_t)b * 8 * 64;
        float* outp = out + ((size_t)(b0 + b) * LEN + (size_t)a * 32) * DIM;
#pragma unroll 4
        for (int i = 0; i < 16; i++) {
            int g4 = i * 256 + t;
            int rr = g4 >> 7;            // local seq row 0..31
            int c  = (g4 & 127) * 4;     // column 0..508
            int ll = rr * 8 + (c >> 6);
            int hh = c & 63;
            float4 a0 = *(const float4*)(attb + ll * 8);
            float4 a1 = *(const float4*)(attb + ll * 8 + 4);
            float av[8] = {a0.x, a0.y, a0.z, a0.w, a1.x, a1.y, a1.z, a1.w};
            float4 o = make_float4(0.f, 0.f, 0.f, 0.f);
#pragma unroll
            for (int r = 0; r < 8; r++) {
                float4 vv = *(const float4*)(vtb + r * 64 + hh);
                o.x += av[r] * vv.x; o.y += av[r] * vv.y;
                o.z += av[r] * vv.z; o.w += av[r] * vv.w;
            }
            *(float4*)(outp + rr * 512 + c) = o;
        }
    }
}

extern "C" void kernel_launch(void* const* d_in, const int* in_sizes, int n_in,
                              void* d_out, int out_size) {
    const float* x      = (const float*)d_in[0];
    const float* Wq     = (const float*)d_in[1];
    const float* bq     = (const float*)d_in[2];
    const float* Wk     = (const float*)d_in[3];
    const float* bk     = (const float*)d_in[4];
    const float* Wv     = (const float*)d_in[5];
    const float* bv     = (const float*)d_in[6];
    const float* factor = (const float*)d_in[7];
    float* out = (float*)d_out;

    cudaFuncSetAttribute(attn_kernel, cudaFuncAttributeMaxDynamicSharedMemorySize, SMEM_BYTES);

    precompute_kernel<<<128, 256>>>(Wk, bk, Wv, bv, factor);
    dim3 grid(16, 64);
    attn_kernel<<<grid, 256, SMEM_BYTES>>>(x, Wq, bq, out);
}

// round 5
// speedup vs baseline: 1.4856x; 1.4856x over previous
#include <cuda_runtime.h>
#include <cstddef>

#define LEN 2048
#define DIM 512

// Precomputed: G[a][p][d][r], a<64, p<2, d<512, r<8  (2MB each)
__device__ float g_Gk[64 * 2 * 512 * 8];
__device__ float g_Gv[64 * 2 * 512 * 8];
__device__ float g_bkf[64 * 2 * 8];
__device__ float g_bvf[64 * 2 * 8];

typedef unsigned long long u64;
__device__ __forceinline__ u64 dup2(float x) {
    u64 r; asm("mov.b64 %0,{%1,%1};" : "=l"(r) : "f"(x)); return r;
}
__device__ __forceinline__ void unpack2(u64 v, float &x, float &y) {
    asm("mov.b64 {%0,%1},%2;" : "=f"(x), "=f"(y) : "l"(v));
}
__device__ __forceinline__ void fma2(u64 &a, u64 b, u64 c) {
    asm("fma.rn.f32x2 %0,%1,%2,%0;" : "+l"(a) : "l"(b), "l"(c));
}

// ================= Kernel 1: G[a][p][d][r] = sum_l W[256p+l,d]*f[a,l,r] =================
__global__ void __launch_bounds__(512) precompute_kernel(
    const float* __restrict__ Wk, const float* __restrict__ bk,
    const float* __restrict__ Wv, const float* __restrict__ bv,
    const float* __restrict__ fac)
{
    __shared__ float f_s[256 * 8];
    __shared__ float bks[256], bvs[256];
    const int a = blockIdx.x >> 1, p = blockIdx.x & 1;
    const int t = threadIdx.x;

    const float* fa = fac + a * (256 * 8);
    for (int i = t; i < 2048; i += 512) f_s[i] = fa[i];
    if (t < 256) { bks[t] = bk[256 * p + t]; bvs[t] = bv[256 * p + t]; }
    __syncthreads();

    const int d = t;
    u64 gk2[4], gv2[4];
#pragma unroll
    for (int q = 0; q < 4; q++) { gk2[q] = 0ull; gv2[q] = 0ull; }

#pragma unroll 4
    for (int l = 0; l < 256; l++) {
        u64 wkd = dup2(__ldg(Wk + (size_t)(256 * p + l) * 512 + d));
        u64 wvd = dup2(__ldg(Wv + (size_t)(256 * p + l) * 512 + d));
        const ulonglong2* fp = (const ulonglong2*)(f_s + l * 8);
        ulonglong2 fA = fp[0], fB = fp[1];
        fma2(gk2[0], wkd, fA.x); fma2(gk2[1], wkd, fA.y);
        fma2(gk2[2], wkd, fB.x); fma2(gk2[3], wkd, fB.y);
        fma2(gv2[0], wvd, fA.x); fma2(gv2[1], wvd, fA.y);
        fma2(gv2[2], wvd, fB.x); fma2(gv2[3], wvd, fB.y);
    }
    ulonglong2* gko = (ulonglong2*)(g_Gk + a * 8192 + p * 4096 + d * 8);
    ulonglong2* gvo = (ulonglong2*)(g_Gv + a * 8192 + p * 4096 + d * 8);
    gko[0] = make_ulonglong2(gk2[0], gk2[1]); gko[1] = make_ulonglong2(gk2[2], gk2[3]);
    gvo[0] = make_ulonglong2(gv2[0], gv2[1]); gvo[1] = make_ulonglong2(gv2[2], gv2[3]);

    if (t < 16) {
        int r = t & 7;
        const float* bb = (t < 8) ? bks : bvs;
        float acc = 0.f;
        for (int l = 0; l < 256; l++) acc += bb[l] * f_s[l * 8 + r];
        if (t < 8) g_bkf[(a * 2 + p) * 8 + r] = acc;
        else       g_bvf[(a * 2 + p) * 8 + r] = acc;
    }
}

// ================= Kernel 2: fused attention, one block per (a, batch-pair) =============
// smem layout (float offsets)
#define OFF_WT   0        // 16512: x tile [32][516] (steps 1-2); 4 Wq tiles [16][258] (step 3)
#define OFF_G    16512    // 16416: G staged [mat 2][p 2][4104] (p block = 512d x 8r + 8 pad)
#define OFF_M    32928    // 16384: m[b 2][kappa 1024][8]
#define OFF_KV   49312    // 2048:  k'/v' [(bi*2+mat)*64 + h][8]
#define OFF_S    51360    // 32
#define OFF_VT   51392    // 1024:  v' transposed [bi*8+r][64]
#define OFF_ATTN 52416    // 4096:  step-1 scratch / attn weights [(b*256+l)][8]
#define OFF_BQ   56512    // 512
#define SMEM_FLOATS 57024
#define SMEM_BYTES (SMEM_FLOATS * 4)
// step-3 split-K partials live in OFF_G (free after step 1): [kg 2][l 256][16]

__device__ __forceinline__ void stage_load(float4* st, const float* __restrict__ Wq,
                                           int kg, int tid, int dbase) {
#pragma unroll
    for (int k2 = 0; k2 < 4; k2++) {
        int f = tid + 256 * k2;
        int l = f >> 2, c4 = f & 3;
        st[k2] = *(const float4*)(Wq + (size_t)(256 * kg + l) * 512 + dbase + c4 * 4);
    }
}
__device__ __forceinline__ void stage_store(const float4* st, float* tb, int tid) {
#pragma unroll
    for (int k2 = 0; k2 < 4; k2++) {
        int f = tid + 256 * k2;
        int l = f >> 2, c4 = f & 3;
        tb[(c4 * 4 + 0) * 258 + l] = st[k2].x;
        tb[(c4 * 4 + 1) * 258 + l] = st[k2].y;
        tb[(c4 * 4 + 2) * 258 + l] = st[k2].z;
        tb[(c4 * 4 + 3) * 258 + l] = st[k2].w;
    }
}

__global__ void __launch_bounds__(512, 1) attn_kernel(
    const float* __restrict__ x, const float* __restrict__ Wq,
    const float* __restrict__ bq, float* __restrict__ out)
{
    extern __shared__ float sm[];
    const int t = threadIdx.x;
    const int a = blockIdx.y;
    const int b0 = blockIdx.x * 2;

    // ---- stage G slab (with bank pads) + bq ----
    {
#pragma unroll
        for (int k = 0; k < 8; k++) {
            int flat = t + 512 * k;            // 4096 float4s total
            int mat = flat >> 11, rest = flat & 2047;
            int p = rest >> 10, i = rest & 1023;
            const float4* src = (const float4*)((mat ? g_Gv : g_Gk) + a * 8192) + p * 1024 + i;
            float4* dst = (float4*)(sm + OFF_G + mat * 8208 + p * 4104) + i;
            *dst = *src;
        }
        sm[OFF_BQ + t] = bq[t];
    }

    // step-1 thread mapping: t = dh*128 + h*2 + mat
    const int mat1 = t & 1, h1 = (t >> 1) & 63, dh = t >> 7;
    const int pp1 = h1 & 1, row1 = h1 >> 1;

    for (int bi = 0; bi < 2; bi++) {
        const int b = b0 + bi;
        __syncthreads();   // guards G/bq staging (bi=0); x reuse + scratch reuse (bi=1)
        {   // load x tile [32][512] -> padded [32][516]
            const float4* xsrc = (const float4*)(x + ((size_t)b * LEN + (size_t)a * 32) * DIM);
#pragma unroll
            for (int k = 0; k < 8; k++) {
                int f = t + 512 * k;
                int r = f >> 7, c4 = f & 127;
                *(float4*)(sm + OFF_WT + r * 516 + c4 * 4) = xsrc[f];
            }
        }
        __syncthreads();

        // step 1 main: partial k'/v'[h][8r] over d-quarter
        {
            const float* gb = sm + OFF_G + mat1 * 8208 + pp1 * 4104 + dh * 1024;
            const float* xr = sm + OFF_WT + row1 * 516 + dh * 128;
            u64 a0 = 0, a1 = 0, a2 = 0, a3 = 0;
#pragma unroll 4
            for (int dl = 0; dl < 128; dl++) {
                u64 xv = dup2(xr[dl]);
                const ulonglong2* g2 = (const ulonglong2*)(gb + dl * 8);
                ulonglong2 gA = g2[0], gB = g2[1];
                fma2(a0, xv, gA.x); fma2(a1, xv, gA.y);
                fma2(a2, xv, gB.x); fma2(a3, xv, gB.y);
            }
            ulonglong2* sd = (ulonglong2*)(sm + OFF_ATTN + dh * 1024 + (t & 127) * 8);
            sd[0] = make_ulonglong2(a0, a1);
            sd[1] = make_ulonglong2(a2, a3);
        }
        __syncthreads();
        // step 1 reduce: sum 4 quarters + bias -> KV, VT
        if (t < 128) {
            int h = t >> 1, mat = t & 1, ppr = h & 1;
            const float* bb = (mat ? g_bvf : g_bkf) + (a * 2 + ppr) * 8;
            float kv[8];
#pragma unroll
            for (int r = 0; r < 8; r++) kv[r] = bb[r];
#pragma unroll
            for (int d4 = 0; d4 < 4; d4++) {
                const float4* q = (const float4*)(sm + OFF_ATTN + d4 * 1024 + t * 8);
                float4 qa = q[0], qb = q[1];
                kv[0] += qa.x; kv[1] += qa.y; kv[2] += qa.z; kv[3] += qa.w;
                kv[4] += qb.x; kv[5] += qb.y; kv[6] += qb.z; kv[7] += qb.w;
            }
            float4* kd = (float4*)(sm + OFF_KV + ((size_t)(bi * 2 + mat) * 64 + h) * 8);
            kd[0] = make_float4(kv[0], kv[1], kv[2], kv[3]);
            kd[1] = make_float4(kv[4], kv[5], kv[6], kv[7]);
            if (mat) {
#pragma unroll
                for (int r = 0; r < 8; r++) sm[OFF_VT + (bi * 8 + r) * 64 + h] = kv[r];
            }
        }
        __syncthreads();

        // step 2: m[bi][p*512+d][r] = sum_j x[j,d] * k'[2j+p,r]   (d = t)
        {
            const int d = t;
            u64 macc[2][4];
#pragma unroll
            for (int p = 0; p < 2; p++)
#pragma unroll
                for (int q = 0; q < 4; q++) macc[p][q] = 0ull;
            const float* xc = sm + OFF_WT + d;
            const float* kvb = sm + OFF_KV + (size_t)(bi * 2) * 64 * 8;
#pragma unroll 2
            for (int j = 0; j < 32; j++) {
                u64 xv = dup2(xc[j * 516]);
#pragma unroll
                for (int p = 0; p < 2; p++) {
                    const ulonglong2* kk = (const ulonglong2*)(kvb + (size_t)(2 * j + p) * 8);
                    ulonglong2 k0 = kk[0], k1 = kk[1];
                    fma2(macc[p][0], xv, k0.x); fma2(macc[p][1], xv, k0.y);
                    fma2(macc[p][2], xv, k1.x); fma2(macc[p][3], xv, k1.y);
                }
            }
#pragma unroll
            for (int p = 0; p < 2; p++) {
                ulonglong2* md = (ulonglong2*)(sm + OFF_M + bi * 8192 + (size_t)(p * 512 + d) * 8);
                md[0] = make_ulonglong2(macc[p][0], macc[p][1]);
                md[1] = make_ulonglong2(macc[p][2], macc[p][3]);
            }
        }
    }
    __syncthreads();

    // s[b][p][r] = sum_j k'[2j+p,r]  (bq fold)
    if (t < 32) {
        int b = t >> 4, p = (t >> 3) & 1, r = t & 7;
        float acc = 0.f;
        for (int j = 0; j < 32; j++)
            acc += sm[OFF_KV + ((size_t)(b * 2) * 64 + 2 * j + p) * 8 + r];
        sm[OFF_S + (b * 2 + p) * 8 + r] = acc;
    }

    // ---- step 3: split-K (kg = p) register-tiled GEMM ----
    const int kg = t >> 8, b3 = (t >> 7) & 1, lp = t & 127;
    const int tid = t & 255;
#define TILE(kgi, buf) (sm + OFF_WT + (buf) * 8256 + (kgi) * 4128)
    u64 acc[2][4];
#pragma unroll
    for (int i = 0; i < 2; i++)
#pragma unroll
        for (int q = 0; q < 4; q++) acc[i][q] = 0ull;

    float4 st[4];
    stage_load(st, Wq, kg, tid, 0);
    stage_store(st, TILE(kg, 0), tid);
    __syncthreads();

    for (int kt = 0; kt < 32; kt++) {
        const int cur = kt & 1;
        if (kt < 31) stage_load(st, Wq, kg, tid, (kt + 1) * 16);
        const float* tl = TILE(kg, cur);
        const ulonglong2* mb =
            (const ulonglong2*)(sm + OFF_M + b3 * 8192 + (size_t)(kg * 512 + kt * 16) * 8);
#pragma unroll
        for (int dd = 0; dd < 16; dd++) {
            float2 w = *(const float2*)(tl + dd * 258 + 2 * lp);
            ulonglong2 mA = mb[dd * 2], mB = mb[dd * 2 + 1];
            u64 w0 = dup2(w.x), w1 = dup2(w.y);
            fma2(acc[0][0], w0, mA.x); fma2(acc[0][1], w0, mA.y);
            fma2(acc[0][2], w0, mB.x); fma2(acc[0][3], w0, mB.y);
            fma2(acc[1][0], w1, mA.x); fma2(acc[1][1], w1, mA.y);
            fma2(acc[1][2], w1, mB.x); fma2(acc[1][3], w1, mB.y);
        }
        if (kt < 31) stage_store(st, TILE(kg, cur ^ 1), tid);
        __syncthreads();
    }
    // write split-K partials to OFF_G region: [kg][l][b*8+r]
    {
        float* part = sm + OFF_G;
#pragma unroll
        for (int i = 0; i < 2; i++) {
            int l = 2 * lp + i;
            ulonglong2* pd = (ulonglong2*)(part + kg * 4096 + l * 16 + b3 * 8);
            pd[0] = make_ulonglong2(acc[i][0], acc[i][1]);
            pd[1] = make_ulonglong2(acc[i][2], acc[i][3]);
        }
    }
    __syncthreads();

    // ---- softmax: thread = (b2, l) ----
    {
        const int b2 = t >> 8, l = t & 255;
        const float* p0 = sm + OFF_G + l * 16 + b2 * 8;
        const float* p1 = p0 + 4096;
        const float bq0 = sm[OFF_BQ + l], bq1 = sm[OFF_BQ + 256 + l];
        const float* s0 = sm + OFF_S + (b2 * 2 + 0) * 8;
        const float* s1 = sm + OFF_S + (b2 * 2 + 1) * 8;
        float f[8];
#pragma unroll
        for (int r = 0; r < 8; r++)
            f[r] = p0[r] + p1[r] + bq0 * s0[r] + bq1 * s1[r];
        float mx = f[0];
#pragma unroll
        for (int r = 1; r < 8; r++) mx = fmaxf(mx, f[r]);
        float e[8], ssum = 0.f;
#pragma unroll
        for (int r = 0; r < 8; r++) { e[r] = __expf((f[r] - mx) * 0.125f); ssum += e[r]; }
        float inv = 1.0f / ssum;
        float4* ad = (float4*)(sm + OFF_ATTN + ((size_t)(b2 * 256 + l)) * 8);
        ad[0] = make_float4(e[0] * inv, e[1] * inv, e[2] * inv, e[3] * inv);
        ad[1] = make_float4(e[4] * inv, e[5] * inv, e[6] * inv, e[7] * inv);
    }
    __syncthreads();

    // ---- step 4: out[l,h] = sum_r attn[l,r]*v'[h,r], coalesced float4 stores ----
#pragma unroll
    for (int b = 0; b < 2; b++) {
        const float* attb = sm + OFF_ATTN + (size_t)b * 256 * 8;
        const float* vtb  = sm + OFF_VT + (size_t)b * 8 * 64;
        float* outp = out + ((size_t)(b0 + b) * LEN + (size_t)a * 32) * DIM;
#pragma unroll 4
        for (int i = 0; i < 8; i++) {
            int g4 = i * 512 + t;
            int rr = g4 >> 7;            // local seq row 0..31
            int c  = (g4 & 127) * 4;     // column 0..508
            int ll = rr * 8 + (c >> 6);
            int hh = c & 63;
            float4 a0 = *(const float4*)(attb + ll * 8);
            float4 a1 = *(const float4*)(attb + ll * 8 + 4);
            float av[8] = {a0.x, a0.y, a0.z, a0.w, a1.x, a1.y, a1.z, a1.w};
            float4 o = make_float4(0.f, 0.f, 0.f, 0.f);
#pragma unroll
            for (int r = 0; r < 8; r++) {
                float4 vv = *(const float4*)(vtb + r * 64 + hh);
                o.x += av[r] * vv.x; o.y += av[r] * vv.y;
                o.z += av[r] * vv.z; o.w += av[r] * vv.w;
            }
            *(float4*)(outp + rr * 512 + c) = o;
        }
    }
}

extern "C" void kernel_launch(void* const* d_in, const int* in_sizes, int n_in,
                              void* d_out, int out_size) {
    const float* x      = (const float*)d_in[0];
    const float* Wq     = (const float*)d_in[1];
    const float* bq     = (const float*)d_in[2];
    const float* Wk     = (const float*)d_in[3];
    const float* bk     = (const float*)d_in[4];
    const float* Wv     = (const float*)d_in[5];
    const float* bv     = (const float*)d_in[6];
    const float* factor = (const float*)d_in[7];
    float* out = (float*)d_out;

    cudaFuncSetAttribute(attn_kernel, cudaFuncAttributeMaxDynamicSharedMemorySize, SMEM_BYTES);

    precompute_kernel<<<128, 512>>>(Wk, bk, Wv, bv, factor);
    dim3 grid(16, 64);
    attn_kernel<<<grid, 512, SMEM_BYTES>>>(x, Wq, bq, out);
}